// round 11
// baseline (speedup 1.0000x reference)
#include <cuda_runtime.h>
#include <cuda_fp16.h>
#include <cstdint>
#include <cstddef>

// KMeansLayer via mma.sync m16n8k16 (fp16 2-way split, 3 passes) + fused softmax.
// out[n,k] = softmax_k( 20*(x_n . c_k) - 10*||c_k||^2 )   (||x||^2 cancels)
// x: [32768, 256] f32, centroids: [512, 256] f32, out: [32768, 512] f32.
// R11: mbarrier full/empty pipeline replaces wait_group+__syncthreads --
//      warps decouple (skew ~1-2 steps) so LDS/cvt phases of one warp overlap
//      MMA bursts of another. MT=32, 256 thr, 2 CTAs/SM (as R10).

#define NRTOT   32768
#define KCLUST  512
#define DDIM    256
#define MT      32          // rows per CTA
#define NK      16          // k16 steps (DDIM/16)
#define NST     3           // pipeline stages
#define NTHR    256
#define LOG2E   1.4426950408889634f

#define A_ROW_F     20      // padded A row stride in floats (80B, 16B-aligned)
#define A_STG_BYTES (MT * A_ROW_F * 4)                   // 2560
#define B_STG_BYTES 32768   // 2 hl * 64 nt * 32 lanes * 8B
#define STG_BYTES   (A_STG_BYTES + B_STG_BYTES)          // 35328
#define OFF_C10     (NST * STG_BYTES)                    // 105984
#define OFF_REDM    (OFF_C10 + 2048)
#define OFF_REDS    (OFF_REDM + 1024)                    // 32 rows * 8 nw * 4B
#define OFF_MBAR    (OFF_REDS + 1024)                    // 6 mbarriers * 8B
#define SMEM_TOTAL  (OFF_MBAR + 64)                      // 110112 (x2 = 220KB/SM)

// device scratch
__device__ float g_csq10[KCLUST];
__device__ uint2 g_Bfrag[NK * 2 * 64 * 32];              // 0.5 MB fp16 B frags

// ---------------------------------------------------------------- helpers
__device__ __forceinline__ uint32_t smem_u32(const void* p) {
    uint32_t a;
    asm("{ .reg .u64 t; cvta.to.shared.u64 t, %1; cvt.u32.u64 %0, t; }"
        : "=r"(a) : "l"(p));
    return a;
}
__device__ __forceinline__ uint32_t packh2(float a, float b) {
    __half2 h = __floats2half2_rn(a, b);
    return *reinterpret_cast<uint32_t*>(&h);
}
__device__ __forceinline__ void cp16(uint32_t dst, const void* src) {
    asm volatile("cp.async.cg.shared.global [%0], [%1], 16;"
                 :: "r"(dst), "l"(__cvta_generic_to_global(src)) : "memory");
}

#define MBAR_INIT(a, c) \
    asm volatile("mbarrier.init.shared.b64 [%0], %1;" :: "r"(a), "r"((uint32_t)(c)) : "memory")
#define MBAR_ARRIVE(a) \
    asm volatile("mbarrier.arrive.shared.b64 _, [%0];" :: "r"(a) : "memory")
#define CP_MBAR_ARRIVE(a) \
    asm volatile("cp.async.mbarrier.arrive.noinc.shared.b64 [%0];" :: "r"(a) : "memory")

__device__ __forceinline__ void mbar_wait(uint32_t mbar, uint32_t parity) {
    asm volatile(
        "{\n\t.reg .pred P;\n\t"
        "WL_%=:\n\t"
        "mbarrier.try_wait.parity.acquire.cta.shared::cta.b64 P, [%0], %1, 0x989680;\n\t"
        "@P bra.uni WD_%=;\n\t"
        "bra.uni WL_%=;\n\t"
        "WD_%=:\n\t}"
        :: "r"(mbar), "r"(parity) : "memory");
}

__device__ __forceinline__ void mma16(float* d, const uint4& a, const uint2& b) {
    asm("mma.sync.aligned.m16n8k16.row.col.f32.f16.f16.f32 "
        "{%0,%1,%2,%3}, {%4,%5,%6,%7}, {%8,%9}, {%0,%1,%2,%3};"
        : "+f"(d[0]), "+f"(d[1]), "+f"(d[2]), "+f"(d[3])
        : "r"(a.x), "r"(a.y), "r"(a.z), "r"(a.w), "r"(b.x), "r"(b.y));
}

// ------------------------------------------------------ prologue: centroids
// One block per cluster n: 10*||c_n||^2 + fp16 hi/lo B fragments.
__global__ void prep_kernel(const float* __restrict__ cent) {
    __shared__ float cs[DDIM];
    __shared__ float part[64];
    const int n = blockIdx.x, t = threadIdx.x;

    if (t < 64) {
        float4 v = reinterpret_cast<const float4*>(cent)[n * (DDIM / 4) + t];
        reinterpret_cast<float4*>(cs)[t] = v;
        part[t] = v.x * v.x + v.y * v.y + v.z * v.z + v.w * v.w;
    }
    __syncthreads();
    if (t < 32) {
        float s = part[t] + part[t + 32];
#pragma unroll
        for (int o = 16; o > 0; o >>= 1) s += __shfl_xor_sync(0xffffffffu, s, o);
        if (t == 0) g_csq10[n] = 10.0f * s;
    }

    const int kc = t >> 3, hl = (t >> 2) & 1, tig = t & 3;
    const int k0 = kc * 16 + 2 * tig;
    const float v[4] = {cs[k0], cs[k0 + 1], cs[k0 + 8], cs[k0 + 9]};
    uint32_t p0, p1;
    if (hl == 0) {
        p0 = packh2(v[0], v[1]);
        p1 = packh2(v[2], v[3]);
    } else {
        float r[4];
#pragma unroll
        for (int i = 0; i < 4; ++i) {
            __half h = __float2half_rn(v[i]);
            r[i] = v[i] - __half2float(h);
        }
        p0 = packh2(r[0], r[1]);
        p1 = packh2(r[2], r[3]);
    }
    const int nt = n >> 3;
    const int lane = (n & 7) * 4 + tig;
    g_Bfrag[((kc * 2 + hl) * 64 + nt) * 32 + lane] = make_uint2(p0, p1);
}

// ------------------------------------------------------------ main kernel
// stage slot: [A raw: 32 rows x 16 floats @ stride 20][B frags: 32KB]
__device__ __forceinline__ void issue_stage(uint32_t sb, int s, int kc,
                                            const float* __restrict__ x,
                                            int rowblk, int tid) {
    const uint32_t dst0 = sb + s * STG_BYTES;
    if (tid < 128) {
        const int row = tid >> 2, part = tid & 3;
        const float* src = x + (size_t)(rowblk * MT + row) * DDIM + kc * 16 + part * 4;
        cp16(dst0 + row * (A_ROW_F * 4) + part * 16, src);
    }
    const char* gB = reinterpret_cast<const char*>(g_Bfrag) +
                     (size_t)kc * B_STG_BYTES;
#pragma unroll
    for (int j = 0; j < 8; ++j) {
        const int o = (tid + j * NTHR) * 16;
        cp16(dst0 + A_STG_BYTES + o, gB + o);
    }
}

__global__ __launch_bounds__(NTHR, 2)
void kmeans_mma(const float* __restrict__ x, float* __restrict__ out) {
    extern __shared__ char smem[];
    const uint32_t sb = smem_u32(smem);
    const int tid = threadIdx.x;
    const int nw = tid >> 5, lane = tid & 31;      // 8 warps, all cover rows 0..31
    const int grp = lane >> 2, tig = lane & 3;
    const int rowblk = blockIdx.x;

    // mbarrier addresses: full[0..2], empty[0..2]
    const uint32_t mbF = sb + OFF_MBAR;
    const uint32_t mbE = sb + OFF_MBAR + 24;

    if (tid == 0) {
#pragma unroll
        for (int s = 0; s < NST; ++s) {
            MBAR_INIT(mbF + s * 8, NTHR);   // all 256 threads' cp.async arrive
            MBAR_INIT(mbE + s * 8, 8);      // one arrive per consumer warp
        }
    }
    float* c10s = reinterpret_cast<float*>(smem + OFF_C10);
    for (int i = tid; i < KCLUST; i += NTHR) c10s[i] = g_csq10[i];
    __syncthreads();   // publish mbarrier init + c10s

    float acc[2][8][4];
#pragma unroll
    for (int mt = 0; mt < 2; ++mt)
#pragma unroll
        for (int nt = 0; nt < 8; ++nt)
#pragma unroll
            for (int r = 0; r < 4; ++r) acc[mt][nt][r] = 0.f;

    // initial productions: stages 0 and 1
    issue_stage(sb, 0, 0, x, rowblk, tid);
    CP_MBAR_ARRIVE(mbF + 0 * 8);
    issue_stage(sb, 1, 1, x, rowblk, tid);
    CP_MBAR_ARRIVE(mbF + 1 * 8);

    for (int k = 0; k < NK; ++k) {
        // ---- produce stage j = k+2 ----
        const int j = k + 2;
        if (j < NK) {
            const int s2 = j % NST;
            if (j >= NST)
                mbar_wait(mbE + s2 * 8, ((j - NST) / NST) & 1);
            issue_stage(sb, s2, j, x, rowblk, tid);
            CP_MBAR_ARRIVE(mbF + s2 * 8);
        }

        // ---- consume stage k ----
        const int sl = k % NST;
        mbar_wait(mbF + sl * 8, (k / NST) & 1);

        const float* sAf = reinterpret_cast<const float*>(smem + sl * STG_BYTES);
        const char*  sB  = smem + sl * STG_BYTES + A_STG_BYTES;

        // A: load raw f32, split into fp16 hi/lo fragments in registers
        uint4 ah[2], al[2];
#pragma unroll
        for (int mt = 0; mt < 2; ++mt) {
            const int R0 = mt * 16 + grp;
            float2 p[4];
            p[0] = *reinterpret_cast<const float2*>(&sAf[(R0 + 0) * A_ROW_F + 2 * tig]);
            p[1] = *reinterpret_cast<const float2*>(&sAf[(R0 + 8) * A_ROW_F + 2 * tig]);
            p[2] = *reinterpret_cast<const float2*>(&sAf[(R0 + 0) * A_ROW_F + 2 * tig + 8]);
            p[3] = *reinterpret_cast<const float2*>(&sAf[(R0 + 8) * A_ROW_F + 2 * tig + 8]);
            uint32_t hreg[4], lreg[4];
#pragma unroll
            for (int r = 0; r < 4; ++r) {
                __half hx = __float2half_rn(p[r].x);
                __half hy = __float2half_rn(p[r].y);
                const float rx = p[r].x - __half2float(hx);
                const float ry = p[r].y - __half2float(hy);
                __half2 hh = __halves2half2(hx, hy);
                hreg[r] = *reinterpret_cast<uint32_t*>(&hh);
                lreg[r] = packh2(rx, ry);
            }
            ah[mt] = make_uint4(hreg[0], hreg[1], hreg[2], hreg[3]);
            al[mt] = make_uint4(lreg[0], lreg[1], lreg[2], lreg[3]);
        }

        // B chunks of 4 n-tiles; pass-major MMA
#pragma unroll
        for (int nc = 0; nc < 2; ++nc) {
            uint2 bh[4], bl[4];
#pragma unroll
            for (int jj = 0; jj < 4; ++jj) {
                const int gnt = nw * 8 + nc * 4 + jj;
                bh[jj] = *reinterpret_cast<const uint2*>(
                    sB + (((0 * 64 + gnt) * 32 + lane) << 3));
                bl[jj] = *reinterpret_cast<const uint2*>(
                    sB + (((1 * 64 + gnt) * 32 + lane) << 3));
            }
#pragma unroll
            for (int jj = 0; jj < 4; ++jj) {        // hi*hi
                mma16(acc[0][nc * 4 + jj], ah[0], bh[jj]);
                mma16(acc[1][nc * 4 + jj], ah[1], bh[jj]);
            }
#pragma unroll
            for (int jj = 0; jj < 4; ++jj) {        // hi*lo
                mma16(acc[0][nc * 4 + jj], ah[0], bl[jj]);
                mma16(acc[1][nc * 4 + jj], ah[1], bl[jj]);
            }
#pragma unroll
            for (int jj = 0; jj < 4; ++jj) {        // lo*hi
                mma16(acc[0][nc * 4 + jj], al[0], bh[jj]);
                mma16(acc[1][nc * 4 + jj], al[1], bh[jj]);
            }
        }

        // release the stage: one arrive per warp
        if (lane == 0) MBAR_ARRIVE(mbE + sl * 8);
    }

    // ---------------- fused softmax epilogue ----------------
#pragma unroll
    for (int mt = 0; mt < 2; ++mt)
#pragma unroll
        for (int nt = 0; nt < 8; ++nt)
#pragma unroll
            for (int r = 0; r < 4; ++r) {
                const int col = nw * 64 + nt * 8 + 2 * tig + (r & 1);
                acc[mt][nt][r] = 20.f * acc[mt][nt][r] - c10s[col];
            }

    float* redM = reinterpret_cast<float*>(smem + OFF_REDM);
    float* redS = reinterpret_cast<float*>(smem + OFF_REDS);

    float mloc[4];
#pragma unroll
    for (int rid = 0; rid < 4; ++rid) {
        const int mt = rid >> 1, rh = rid & 1;
        float m = -1e30f;
#pragma unroll
        for (int nt = 0; nt < 8; ++nt) {
            m = fmaxf(m, acc[mt][nt][rh * 2 + 0]);
            m = fmaxf(m, acc[mt][nt][rh * 2 + 1]);
        }
        m = fmaxf(m, __shfl_xor_sync(0xffffffffu, m, 1));
        m = fmaxf(m, __shfl_xor_sync(0xffffffffu, m, 2));
        float s = 0.f;
#pragma unroll
        for (int nt = 0; nt < 8; ++nt) {
#pragma unroll
            for (int c = 0; c < 2; ++c) {
                const float e = exp2f((acc[mt][nt][rh * 2 + c] - m) * LOG2E);
                acc[mt][nt][rh * 2 + c] = e;     // reuse regs as exp values
                s += e;
            }
        }
        s += __shfl_xor_sync(0xffffffffu, s, 1);
        s += __shfl_xor_sync(0xffffffffu, s, 2);
        mloc[rid] = m;
        if (tig == 0) {
            const int row = mt * 16 + rh * 8 + grp;
            redM[row * 8 + nw] = m;
            redS[row * 8 + nw] = s;
        }
    }
    __syncthreads();

#pragma unroll
    for (int rid = 0; rid < 4; ++rid) {
        const int mt = rid >> 1, rh = rid & 1;
        const int row = mt * 16 + rh * 8 + grp;
        float M = -1e30f;
        float mv[8];
#pragma unroll
        for (int j = 0; j < 8; ++j) {
            mv[j] = redM[row * 8 + j];
            M = fmaxf(M, mv[j]);
        }
        float S = 0.f;
#pragma unroll
        for (int j = 0; j < 8; ++j)
            S += redS[row * 8 + j] * exp2f((mv[j] - M) * LOG2E);
        const float scale = exp2f((mloc[rid] - M) * LOG2E) / S;

        float* orow = out + (size_t)(rowblk * MT + row) * KCLUST + nw * 64;
#pragma unroll
        for (int nt = 0; nt < 8; ++nt) {
            float2 v;
            v.x = acc[mt][nt][rh * 2 + 0] * scale;
            v.y = acc[mt][nt][rh * 2 + 1] * scale;
            *reinterpret_cast<float2*>(orow + nt * 8 + 2 * tig) = v;
        }
    }
}

// ---------------------------------------------------------------- launch
extern "C" void kernel_launch(void* const* d_in, const int* in_sizes, int n_in,
                              void* d_out, int out_size) {
    const float* x = (const float*)d_in[0];
    const float* cent = (const float*)d_in[1];
    if (n_in >= 2 && in_sizes[0] == KCLUST * DDIM && in_sizes[1] == NRTOT * DDIM) {
        const float* t = x; x = cent; cent = t;
    }
    float* out = (float*)d_out;

    cudaFuncSetAttribute(kmeans_mma,
                         cudaFuncAttributeMaxDynamicSharedMemorySize,
                         SMEM_TOTAL);

    prep_kernel<<<KCLUST, 128>>>(cent);
    kmeans_mma<<<NRTOT / MT, NTHR, SMEM_TOTAL>>>(x, out);
}